// round 10
// baseline (speedup 1.0000x reference)
#include <cuda_runtime.h>
#include <cstdint>

typedef unsigned long long u64;

// DeformConv3d: B=2, Cin=32, Cout=64, D=8, H=W=48, 3x3x3, s1, p1, d1.
#define CIN     32
#define COUT    64
#define DDIM    8
#define HDIM    48
#define WDIM    48
#define KTAPS   27
#define POSB    128                // positions per block
#define THREADS 256                // 128 consumers + 128 producers
#define PLANE   (HDIM * WDIM)      // 2304
#define SPATIAL (DDIM * PLANE)     // 18432
#define BATCH   2

// channels-last x: g_xT[b][sp][c]
__device__ float g_xT[BATCH * SPATIAL * CIN];
// dup'd weights: per (k,cin): 4 blocks q of 128B; u64 slot = ct*2+p holds
// dup(w[co]) with co = ct*8 + q*2 + p.  One warp LDG.128 = exactly 1 line.
__device__ u64 g_wd[KTAPS * CIN * COUT];

#define BAR_SYNC(id)   asm volatile("bar.sync %0, 256;"   :: "r"(id) : "memory")
#define BAR_ARRIVE(id) asm volatile("bar.arrive %0, 256;" :: "r"(id) : "memory")

// ---- merged prep: blocks [0,576) transpose x; rest build dup'd weights ----
__global__ __launch_bounds__(256) void prep_kernel(const float* __restrict__ x,
                                                   const float* __restrict__ w) {
    const int t = threadIdx.x;
    if (blockIdx.x < BATCH * (SPATIAL / 64)) {
        __shared__ float s_t[CIN * 65];
        const int blk = blockIdx.x;
        const int b   = blk / (SPATIAL / 64);
        const int sp0 = (blk - b * (SPATIAL / 64)) * 64;
        const float* xb = x + b * (CIN * SPATIAL);
        #pragma unroll
        for (int i = t; i < CIN * 64; i += 256) {
            int c = i >> 6, s = i & 63;
            s_t[c * 65 + s] = xb[c * SPATIAL + sp0 + s];
        }
        __syncthreads();
        float* ob = g_xT + (b * SPATIAL + sp0) * CIN;
        #pragma unroll
        for (int i = t; i < CIN * 64; i += 256) {
            int s = i >> 5, c = i & 31;
            ob[s * CIN + c] = s_t[c * 65 + s];
        }
    } else {
        int i = (blockIdx.x - BATCH * (SPATIAL / 64)) * 256 + t;
        if (i < KTAPS * CIN * COUT) {
            int k   = i / (CIN * COUT);
            int r   = i - k * (CIN * COUT);
            int cin = r >> 6;
            int m   = r & 63;                 // within (k,cin): [q][ct][p]
            int q   = m >> 4;
            int ct  = (m >> 1) & 7;
            int p   = m & 1;
            int co  = ct * 8 + q * 2 + p;
            float v = w[co * (CIN * KTAPS) + cin * KTAPS + k];
            uint32_t ub = __float_as_uint(v);
            g_wd[i] = ((u64)ub << 32) | ub;
        }
    }
}

__global__ __launch_bounds__(THREADS, 2) void dcn3d_kernel(
    const float* __restrict__ offs,
    const float* __restrict__ mask,
    const float* __restrict__ bias,
    float* __restrict__ out)
{
    // double-buffered sampled values: [buf][cin][128 pos] (pos-quad XOR swizzle)
    __shared__ float s_val[2][CIN * 128];

    const int t = threadIdx.x;

    const int blkP = blockIdx.x * POSB;
    const int b    = blkP / SPATIAL;
    const int spb  = blkP - b * SPATIAL;

    if (t >= 128) {
        // =================== PRODUCER warps (sampling) ===================
        const int tp = t - 128;
        const int cq = tp & 7;           // channel quad
        const int pa = tp >> 3;          // pos base (0..15), posl = pa + 16u

        const float* offb = offs + b * (2 * KTAPS * SPATIAL) + spb;
        const float* mb   = mask + b * (KTAPS * SPATIAL) + spb;
        const float* xTb  = g_xT + (size_t)b * (SPATIAL * CIN);

        int dout_u[8], ho_u[8], wo_u[8];
        #pragma unroll
        for (int u = 0; u < 8; u++) {
            const int posl = pa + 16 * u;
            const int sp   = spb + posl;
            const int dd   = sp / PLANE;
            const int r2   = sp - dd * PLANE;
            dout_u[u] = dd;
            ho_u[u]   = r2 / WDIM;
            wo_u[u]   = r2 - (r2 / WDIM) * WDIM;
        }
        const int sq_base = pa >> 2;
        const int sr      = pa & 3;

        for (int k = 0; k < KTAPS; k++) {
            const int kd = k / 9;
            const int kh = (k - kd * 9) / 3;
            const int kw = k - kd * 9 - kh * 3;
            const int buf = k & 1;

            if (k >= 2) BAR_SYNC(3 + buf);      // wait buffer empty

            float* sv = s_val[buf];

            #pragma unroll
            for (int u = 0; u < 8; u++) {
                const int posl = pa + 16 * u;
                const int dout = dout_u[u];
                const int ho   = ho_u[u];
                const int wo   = wo_u[u];

                const float oh = offb[(2 * k)     * SPATIAL + posl];
                const float ow = offb[(2 * k + 1) * SPATIAL + posl];
                const float m  = mb[k * SPATIAL + posl];

                const int  dp  = kd + dout - 1;
                const bool vdd = (dp >= 0) && (dp < DDIM);
                const int  di  = min(max(dp, 0), DDIM - 1);

                const float h = (float)(kh + ho - 1) + oh;
                const float w = (float)(kw + wo - 1) + ow;
                const float h0f = floorf(h), w0f = floorf(w);
                const float lh = h - h0f, lw = w - w0f;
                const int h0 = (int)h0f, w0 = (int)w0f;
                const int h1 = h0 + 1,   w1 = w0 + 1;

                const bool bh0 = (h0 >= 0) && (h0 < HDIM);
                const bool bh1 = (h1 >= 0) && (h1 < HDIM);
                const bool bw0 = (w0 >= 0) && (w0 < WDIM);
                const bool bw1 = (w1 >= 0) && (w1 < WDIM);

                const float w00 = (1.f - lh) * (1.f - lw) * ((bh0 && bw0 && vdd) ? m : 0.f);
                const float w01 = (1.f - lh) * lw         * ((bh0 && bw1 && vdd) ? m : 0.f);
                const float w10 = lh * (1.f - lw)         * ((bh1 && bw0 && vdd) ? m : 0.f);
                const float w11 = lh * lw                 * ((bh1 && bw1 && vdd) ? m : 0.f);

                const int hc0 = min(max(h0, 0), HDIM - 1);
                const int hc1 = min(max(h1, 0), HDIM - 1);
                const int wc0 = min(max(w0, 0), WDIM - 1);
                const int wc1 = min(max(w1, 0), WDIM - 1);

                const float* base = xTb + (size_t)di * (PLANE * CIN) + cq * 4;
                const float4 c00 = *(const float4*)(base + (size_t)(hc0 * WDIM + wc0) * CIN);
                const float4 c01 = *(const float4*)(base + (size_t)(hc0 * WDIM + wc1) * CIN);
                const float4 c10 = *(const float4*)(base + (size_t)(hc1 * WDIM + wc0) * CIN);
                const float4 c11 = *(const float4*)(base + (size_t)(hc1 * WDIM + wc1) * CIN);

                float4 v;
                v.x = fmaf(w00, c00.x, fmaf(w01, c01.x, fmaf(w10, c10.x, w11 * c11.x)));
                v.y = fmaf(w00, c00.y, fmaf(w01, c01.y, fmaf(w10, c10.y, w11 * c11.y)));
                v.z = fmaf(w00, c00.z, fmaf(w01, c01.z, fmaf(w10, c10.z, w11 * c11.z)));
                v.w = fmaf(w00, c00.w, fmaf(w01, c01.w, fmaf(w10, c10.w, w11 * c11.w)));

                // swizzled scatter: cin = cq*4 + c, perm(cin) = (c<<3)|cq
                const int sq = sq_base + 4 * u;
                const float vv[4] = {v.x, v.y, v.z, v.w};
                #pragma unroll
                for (int c = 0; c < 4; c++) {
                    const int perm = (c << 3) | cq;
                    sv[(cq * 4 + c) * 128 + ((sq ^ perm) << 2) + sr] = vv[c];
                }
            }

            // bar.sync drains pending STS (HW-native) and releases consumers.
            BAR_SYNC(1 + buf);
        }
    } else {
        // =================== CONSUMER warps (GEMM) ===================
        const int ct = t & 7;            // co tile (co = ct*8 + j)
        const int pt = t >> 3;           // pos tile (pos = pt*8 + i)
        const int Q0 = 2 * pt;
        const int Q1 = 2 * pt + 1;

        u64 acc[8][4];
        #pragma unroll
        for (int j = 0; j < 8; j++)
            #pragma unroll
            for (int pp = 0; pp < 4; pp++) acc[j][pp] = 0ULL;

        for (int k = 0; k < KTAPS; k++) {
            const int buf = k & 1;
            BAR_SYNC(1 + buf);                          // wait buffer full

            const float* sv = s_val[buf];

            #pragma unroll
            for (int cin = 0; cin < CIN; cin++) {
                const int perm = ((cin & 3) << 3) | (cin >> 2);
                const float4 a0 = *(const float4*)(sv + cin * 128 + ((Q0 ^ perm) << 2));
                const float4 a1 = *(const float4*)(sv + cin * 128 + ((Q1 ^ perm) << 2));
                const u64 p0 = ((const u64*)&a0)[0];
                const u64 p1 = ((const u64*)&a0)[1];
                const u64 p2 = ((const u64*)&a1)[0];
                const u64 p3 = ((const u64*)&a1)[1];

                // 4 LDG.128, each = one 128B line per warp, all data dup'd pairs
                const ulonglong2* wq =
                    (const ulonglong2*)g_wd + ((size_t)(k * CIN + cin) << 5) + ct;
                const ulonglong2 wA = wq[0];    // co j=0,1
                const ulonglong2 wB = wq[8];    // j=2,3
                const ulonglong2 wC = wq[16];   // j=4,5
                const ulonglong2 wD = wq[24];   // j=6,7
                const u64 wd[8] = {wA.x, wA.y, wB.x, wB.y,
                                   wC.x, wC.y, wD.x, wD.y};
                #pragma unroll
                for (int j = 0; j < 8; j++) {
                    asm("fma.rn.f32x2 %0, %1, %2, %0;" : "+l"(acc[j][0]) : "l"(p0), "l"(wd[j]));
                    asm("fma.rn.f32x2 %0, %1, %2, %0;" : "+l"(acc[j][1]) : "l"(p1), "l"(wd[j]));
                    asm("fma.rn.f32x2 %0, %1, %2, %0;" : "+l"(acc[j][2]) : "l"(p2), "l"(wd[j]));
                    asm("fma.rn.f32x2 %0, %1, %2, %0;" : "+l"(acc[j][3]) : "l"(p3), "l"(wd[j]));
                }
            }

            BAR_ARRIVE(3 + buf);                        // signal buffer empty
        }

        // ---- epilogue: pos [spb+pt*8, +8), co [ct*8, +8) ----
        float* ob = out + (size_t)b * (COUT * SPATIAL) + spb + pt * 8;
        #pragma unroll
        for (int j = 0; j < 8; j++) {
            const int co = ct * 8 + j;
            const float bv = __ldg(&bias[co]);
            float f[8];
            #pragma unroll
            for (int pp = 0; pp < 4; pp++) {
                asm("mov.b64 {%0, %1}, %2;"
                    : "=f"(f[2 * pp]), "=f"(f[2 * pp + 1]) : "l"(acc[j][pp]));
            }
            float4 o0, o1;
            o0.x = f[0] + bv; o0.y = f[1] + bv; o0.z = f[2] + bv; o0.w = f[3] + bv;
            o1.x = f[4] + bv; o1.y = f[5] + bv; o1.z = f[6] + bv; o1.w = f[7] + bv;
            *(float4*)(ob + (size_t)co * SPATIAL)     = o0;
            *(float4*)(ob + (size_t)co * SPATIAL + 4) = o1;
        }
    }
}

extern "C" void kernel_launch(void* const* d_in, const int* in_sizes, int n_in,
                              void* d_out, int out_size)
{
    const float* x    = (const float*)d_in[0];
    const float* offs = (const float*)d_in[1];
    const float* mask = (const float*)d_in[2];
    const float* w    = (const float*)d_in[3];
    const float* bias = (const float*)d_in[4];
    float* out = (float*)d_out;

    const int nprep = BATCH * (SPATIAL / 64) + (KTAPS * CIN * COUT + 255) / 256;
    prep_kernel<<<nprep, 256>>>(x, w);

    const int nblocks = (BATCH * SPATIAL) / POSB;   // 288
    dcn3d_kernel<<<nblocks, THREADS>>>(offs, mask, bias, out);
}

// round 12
// speedup vs baseline: 1.8404x; 1.8404x over previous
#include <cuda_runtime.h>
#include <cstdint>

typedef unsigned long long u64;

// DeformConv3d: B=2, Cin=32, Cout=64, D=8, H=W=48, 3x3x3, s1, p1, d1.
#define CIN     32
#define COUT    64
#define DDIM    8
#define HDIM    48
#define WDIM    48
#define KTAPS   27
#define POSB    128                // positions per block
#define THREADS 256
#define PLANE   (HDIM * WDIM)      // 2304
#define SPATIAL (DDIM * PLANE)     // 18432
#define BATCH   2
#define WTAP    (CIN * COUT)       // 2048

// channels-last x: g_xT[b][sp][c]
__device__ float g_xT[BATCH * SPATIAL * CIN];
// weights: g_wp[k][cin][co]
__device__ float g_wp[KTAPS * WTAP];

// ---- merged prep: blocks [0,576) transpose x; rest lay out weights ----
__global__ __launch_bounds__(256) void prep_kernel(const float* __restrict__ x,
                                                   const float* __restrict__ w) {
    const int t = threadIdx.x;
    if (blockIdx.x < BATCH * (SPATIAL / 64)) {
        __shared__ float s_t[CIN * 65];
        const int blk = blockIdx.x;
        const int b   = blk / (SPATIAL / 64);
        const int sp0 = (blk - b * (SPATIAL / 64)) * 64;
        const float* xb = x + b * (CIN * SPATIAL);
        #pragma unroll
        for (int i = t; i < CIN * 64; i += 256) {
            int c = i >> 6, s = i & 63;
            s_t[c * 65 + s] = xb[c * SPATIAL + sp0 + s];
        }
        __syncthreads();
        float* ob = g_xT + (b * SPATIAL + sp0) * CIN;
        #pragma unroll
        for (int i = t; i < CIN * 64; i += 256) {
            int s = i >> 5, c = i & 31;
            ob[s * CIN + c] = s_t[c * 65 + s];
        }
    } else {
        int i = (blockIdx.x - BATCH * (SPATIAL / 64)) * 256 + t;
        if (i < KTAPS * WTAP) {
            int k   = i / WTAP;
            int r   = i - k * WTAP;
            int cin = r >> 6;
            int co  = r & 63;
            g_wp[i] = w[co * (CIN * KTAPS) + cin * KTAPS + k];
        }
    }
}

__device__ __forceinline__ u64 dup_f32x2(float v) {
    u64 r;
    asm("mov.b64 %0, {%1, %1};" : "=l"(r) : "f"(v));
    return r;
}

// gather one (pos, cq) unit for tap kn: issue corner loads, compute bilinear coeffs
__device__ __forceinline__ void gather_unit(
    int kd, int kh, int kw, int kn, int posl, int dout, int ho, int wo,
    const float* __restrict__ offb, const float* __restrict__ mb,
    const float* __restrict__ xTb, int cq,
    float4 cor[4], float bw[4])
{
    const float oh = offb[(2 * kn) * SPATIAL + posl];
    const float ow = offb[(2 * kn + 1) * SPATIAL + posl];
    const float m  = mb[kn * SPATIAL + posl];

    const int  dp  = kd + dout - 1;
    const bool vdd = (dp >= 0) && (dp < DDIM);
    const int  di  = min(max(dp, 0), DDIM - 1);

    const float h = (float)(kh + ho - 1) + oh;
    const float w = (float)(kw + wo - 1) + ow;
    const float h0f = floorf(h), w0f = floorf(w);
    const float lh = h - h0f, lw = w - w0f;
    const int h0 = (int)h0f, w0 = (int)w0f;
    const int h1 = h0 + 1,   w1 = w0 + 1;

    const bool bh0 = (h0 >= 0) && (h0 < HDIM);
    const bool bh1 = (h1 >= 0) && (h1 < HDIM);
    const bool bw0 = (w0 >= 0) && (w0 < WDIM);
    const bool bw1 = (w1 >= 0) && (w1 < WDIM);

    bw[0] = (1.f - lh) * (1.f - lw) * ((bh0 && bw0 && vdd) ? m : 0.f);
    bw[1] = (1.f - lh) * lw         * ((bh0 && bw1 && vdd) ? m : 0.f);
    bw[2] = lh * (1.f - lw)         * ((bh1 && bw0 && vdd) ? m : 0.f);
    bw[3] = lh * lw                 * ((bh1 && bw1 && vdd) ? m : 0.f);

    const int hc0 = min(max(h0, 0), HDIM - 1);
    const int hc1 = min(max(h1, 0), HDIM - 1);
    const int wc0 = min(max(w0, 0), WDIM - 1);
    const int wc1 = min(max(w1, 0), WDIM - 1);

    const float* base = xTb + (size_t)di * (PLANE * CIN) + cq * 4;
    cor[0] = *(const float4*)(base + (size_t)(hc0 * WDIM + wc0) * CIN);
    cor[1] = *(const float4*)(base + (size_t)(hc0 * WDIM + wc1) * CIN);
    cor[2] = *(const float4*)(base + (size_t)(hc1 * WDIM + wc0) * CIN);
    cor[3] = *(const float4*)(base + (size_t)(hc1 * WDIM + wc1) * CIN);
}

__device__ __forceinline__ float4 combine_unit(const float4 cor[4], const float bw[4]) {
    float4 v;
    v.x = fmaf(bw[0], cor[0].x, fmaf(bw[1], cor[1].x, fmaf(bw[2], cor[2].x, bw[3] * cor[3].x)));
    v.y = fmaf(bw[0], cor[0].y, fmaf(bw[1], cor[1].y, fmaf(bw[2], cor[2].y, bw[3] * cor[3].y)));
    v.z = fmaf(bw[0], cor[0].z, fmaf(bw[1], cor[1].z, fmaf(bw[2], cor[2].z, bw[3] * cor[3].z)));
    v.w = fmaf(bw[0], cor[0].w, fmaf(bw[1], cor[1].w, fmaf(bw[2], cor[2].w, bw[3] * cor[3].w)));
    return v;
}

__device__ __forceinline__ void gemm_half(
    const float* __restrict__ svp, const float* __restrict__ swp,
    int c0, int pt, int ct4, u64 acc[4][4])
{
    #pragma unroll
    for (int cin = c0; cin < c0 + 16; cin++) {
        const int s = cin & 28;                       // swizzle (= 4*cq)
        const float4 a0 = *(const float4*)(svp + cin * 128 + ((pt * 8) ^ s));
        const float4 a1 = *(const float4*)(svp + cin * 128 + ((pt * 8 + 4) ^ s));
        const u64 p[4] = {((const u64*)&a0)[0], ((const u64*)&a0)[1],
                          ((const u64*)&a1)[0], ((const u64*)&a1)[1]};
        const float4 wq = *(const float4*)(swp + cin * 64 + ct4 * 4);
        const float wj[4] = {wq.x, wq.y, wq.z, wq.w};
        #pragma unroll
        for (int j = 0; j < 4; j++) {
            const u64 wd = dup_f32x2(wj[j]);
            #pragma unroll
            for (int pp = 0; pp < 4; pp++) {
                asm("fma.rn.f32x2 %0, %1, %2, %0;"
                    : "+l"(acc[pp][j]) : "l"(p[pp]), "l"(wd));
            }
        }
    }
}

__global__ __launch_bounds__(THREADS, 2) void dcn3d_kernel(
    const float* __restrict__ offs,
    const float* __restrict__ mask,
    const float* __restrict__ bias,
    float* __restrict__ out)
{
    __shared__ float s_v[2][CIN * 128];   // sampled vals, swizzled  (32 KB)
    __shared__ float s_w[2][WTAP];        // tap weights            (16 KB)

    const int t   = threadIdx.x;
    const int cq  = t & 7;                // sampling: channel quad
    const int pa  = t >> 3;               // sampling: pos base (0..31), posl = pa+32u
    const int ct4 = t & 15;               // GEMM: co quad (co = ct4*4 + j)
    const int pt  = t >> 4;               // GEMM: pos octet (pos = pt*8 + i)

    const int blkP = blockIdx.x * POSB;
    const int b    = blkP / SPATIAL;
    const int spb  = blkP - b * SPATIAL;

    const float* offb = offs + b * (2 * KTAPS * SPATIAL) + spb;
    const float* mb   = mask + b * (KTAPS * SPATIAL) + spb;
    const float* xTb  = g_xT + (size_t)b * (SPATIAL * CIN);

    // per-unit spatial decomposition (fixed across taps)
    int dout_u[4], ho_u[4], wo_u[4];
    #pragma unroll
    for (int u = 0; u < 4; u++) {
        const int posl = pa + 32 * u;
        const int sp   = spb + posl;
        const int dd   = sp / PLANE;
        const int r2   = sp - dd * PLANE;
        dout_u[u] = dd;
        ho_u[u]   = r2 / WDIM;
        wo_u[u]   = r2 - (r2 / WDIM) * WDIM;
    }

    float4 sv[4];        // sampled values for current tap
    float4 wreg[2];      // staged weights for tap k+1

    // ---- prologue: weights tap0 -> s_w[0]; weights tap1 -> regs; sample tap0 ----
    {
        const float4* w0 = (const float4*)g_wp;
        ((float4*)s_w[0])[t * 2]     = __ldg(w0 + t * 2);
        ((float4*)s_w[0])[t * 2 + 1] = __ldg(w0 + t * 2 + 1);
        const float4* w1 = (const float4*)(g_wp + WTAP);
        wreg[0] = __ldg(w1 + t * 2);
        wreg[1] = __ldg(w1 + t * 2 + 1);
    }
    {
        float4 cor[4]; float bwc[4];
        #pragma unroll
        for (int u = 0; u < 4; u++) {
            gather_unit(0, 0, 0, 0, pa + 32 * u, dout_u[u], ho_u[u], wo_u[u],
                        offb, mb, xTb, cq, cor, bwc);
            sv[u] = combine_unit(cor, bwc);
        }
    }

    u64 acc[4][4];                        // [pospair][co j]
    #pragma unroll
    for (int pp = 0; pp < 4; pp++)
        #pragma unroll
        for (int j = 0; j < 4; j++) acc[pp][j] = 0ULL;

    for (int k = 0; k < KTAPS; k++) {
        const int buf = k & 1;
        const int nb  = buf ^ 1;

        // 1) STS sampled values (swizzled: bank = (pa ^ 4cq)&31, conflict-free)
        {
            float* svd = s_v[buf];
            #pragma unroll
            for (int u = 0; u < 4; u++) {
                const int px = (pa + 32 * u) ^ (cq * 4);
                const float vv[4] = {sv[u].x, sv[u].y, sv[u].z, sv[u].w};
                #pragma unroll
                for (int c = 0; c < 4; c++)
                    svd[(cq * 4 + c) * 128 + px] = vv[c];
            }
        }
        // 2) STS weights for tap k+1 into the other buffer
        ((float4*)s_w[nb])[t * 2]     = wreg[0];
        ((float4*)s_w[nb])[t * 2 + 1] = wreg[1];

        __syncthreads();   // drains STS; everyone sees s_v[buf] + s_w[nb]

        // 3) LDG weights tap k+2
        {
            const int k2 = min(k + 2, KTAPS - 1);
            const float4* ws = (const float4*)(g_wp + k2 * WTAP);
            wreg[0] = __ldg(ws + t * 2);
            wreg[1] = __ldg(ws + t * 2 + 1);
        }

        // 4) interleaved: gathers for tap k+1 overlap GEMM of tap k
        const int kn  = min(k + 1, KTAPS - 1);
        const int kd1 = kn / 9;
        const int kh1 = (kn - kd1 * 9) / 3;
        const int kw1 = kn - kd1 * 9 - kh1 * 3;

        const float* svp = s_v[buf];
        const float* swp = s_w[buf];

        {
            float4 corA[4], corB[4]; float bwA[4], bwB[4];
            gather_unit(kd1, kh1, kw1, kn, pa, dout_u[0], ho_u[0], wo_u[0],
                        offb, mb, xTb, cq, corA, bwA);
            gather_unit(kd1, kh1, kw1, kn, pa + 32, dout_u[1], ho_u[1], wo_u[1],
                        offb, mb, xTb, cq, corB, bwB);
            gemm_half(svp, swp, 0, pt, ct4, acc);
            sv[0] = combine_unit(corA, bwA);
            sv[1] = combine_unit(corB, bwB);
        }
        {
            float4 corA[4], corB[4]; float bwA[4], bwB[4];
            gather_unit(kd1, kh1, kw1, kn, pa + 64, dout_u[2], ho_u[2], wo_u[2],
                        offb, mb, xTb, cq, corA, bwA);
            gather_unit(kd1, kh1, kw1, kn, pa + 96, dout_u[3], ho_u[3], wo_u[3],
                        offb, mb, xTb, cq, corB, bwB);
            gemm_half(svp, swp, 16, pt, ct4, acc);
            sv[2] = combine_unit(corA, bwA);
            sv[3] = combine_unit(corB, bwB);
        }

        // 5) WAR guard: nobody may overwrite s_w[buf]/s_v[buf] (next taps'
        //    stores) until all threads finished the GEMM reads above.
        __syncthreads();
    }

    // ---- epilogue: pos [spb+pt*8, +8), co [ct4*4, +4) ----
    float* ob = out + (size_t)b * (COUT * SPATIAL) + spb + pt * 8;
    #pragma unroll
    for (int j = 0; j < 4; j++) {
        const int co = ct4 * 4 + j;
        const float bv = __ldg(&bias[co]);
        float f[8];
        #pragma unroll
        for (int pp = 0; pp < 4; pp++) {
            asm("mov.b64 {%0, %1}, %2;"
                : "=f"(f[2 * pp]), "=f"(f[2 * pp + 1]) : "l"(acc[pp][j]));
        }
        float4 o0, o1;
        o0.x = f[0] + bv; o0.y = f[1] + bv; o0.z = f[2] + bv; o0.w = f[3] + bv;
        o1.x = f[4] + bv; o1.y = f[5] + bv; o1.z = f[6] + bv; o1.w = f[7] + bv;
        *(float4*)(ob + (size_t)co * SPATIAL)     = o0;
        *(float4*)(ob + (size_t)co * SPATIAL + 4) = o1;
    }
}

extern "C" void kernel_launch(void* const* d_in, const int* in_sizes, int n_in,
                              void* d_out, int out_size)
{
    const float* x    = (const float*)d_in[0];
    const float* offs = (const float*)d_in[1];
    const float* mask = (const float*)d_in[2];
    const float* w    = (const float*)d_in[3];
    const float* bias = (const float*)d_in[4];
    float* out = (float*)d_out;

    const int nprep = BATCH * (SPATIAL / 64) + (KTAPS * WTAP + 255) / 256;
    prep_kernel<<<nprep, 256>>>(x, w);

    const int nblocks = (BATCH * SPATIAL) / POSB;   // 288
    dcn3d_kernel<<<nblocks, THREADS>>>(offs, mask, bias, out);
}